// round 1
// baseline (speedup 1.0000x reference)
#include <cuda_runtime.h>

#define NTHREADS 128

// ---------------------------------------------------------------------------
// Packed f32x2 FMA: acc{A,B}[q] each hold outputs (2q, 2q+1) as packed fp32x2.
// wrow points at w[k][0..63] in shared memory (256B aligned).
// ---------------------------------------------------------------------------
static __device__ __forceinline__ void fma_tap(unsigned long long* accA,
                                               unsigned long long* accB,
                                               const float* __restrict__ wrow,
                                               float xa, float xb)
{
    unsigned long long xxA, xxB;
    unsigned ua = __float_as_uint(xa);
    unsigned ub = __float_as_uint(xb);
    asm("mov.b64 %0, {%1, %1};" : "=l"(xxA) : "r"(ua));
    asm("mov.b64 %0, {%1, %1};" : "=l"(xxB) : "r"(ub));
#pragma unroll
    for (int q = 0; q < 16; ++q) {
        ulonglong2 wv = *reinterpret_cast<const ulonglong2*>(wrow + q * 4);
        asm("fma.rn.f32x2 %0, %1, %2, %0;" : "+l"(accA[2 * q])     : "l"(xxA), "l"(wv.x));
        asm("fma.rn.f32x2 %0, %1, %2, %0;" : "+l"(accA[2 * q + 1]) : "l"(xxA), "l"(wv.y));
        asm("fma.rn.f32x2 %0, %1, %2, %0;" : "+l"(accB[2 * q])     : "l"(xxB), "l"(wv.x));
        asm("fma.rn.f32x2 %0, %1, %2, %0;" : "+l"(accB[2 * q + 1]) : "l"(xxB), "l"(wv.y));
    }
}

// relu -> softmax -> scale by center pixel -> pixel-shuffled store
static __device__ __forceinline__ void finish_pos(float* __restrict__ out,
                                                  int n, int gi, int gj,
                                                  unsigned long long* acc,
                                                  float xsel)
{
    float v[64];
#pragma unroll
    for (int q = 0; q < 32; ++q) {
        unsigned lo, hi;
        asm("mov.b64 {%0, %1}, %2;" : "=r"(lo), "=r"(hi) : "l"(acc[q]));
        v[2 * q]     = fmaxf(__uint_as_float(lo), 0.0f);
        v[2 * q + 1] = fmaxf(__uint_as_float(hi), 0.0f);
    }
    float mx = v[0];
#pragma unroll
    for (int o = 1; o < 64; ++o) mx = fmaxf(mx, v[o]);
    float sum = 0.0f;
#pragma unroll
    for (int o = 0; o < 64; ++o) {
        v[o] = __expf(v[o] - mx);
        sum += v[o];
    }
    float scale = xsel / sum;

    // out[n, 1, gi*8 + a, gj*8 + b] = scale * v[a*8+b], row stride 512
    float* base = out + ((size_t)n << 18) + (size_t)(gi * 8) * 512 + gj * 8;
#pragma unroll
    for (int a = 0; a < 8; ++a) {
        float4 t0 = make_float4(scale * v[a * 8 + 0], scale * v[a * 8 + 1],
                                scale * v[a * 8 + 2], scale * v[a * 8 + 3]);
        float4 t1 = make_float4(scale * v[a * 8 + 4], scale * v[a * 8 + 5],
                                scale * v[a * 8 + 6], scale * v[a * 8 + 7]);
        *reinterpret_cast<float4*>(base + (size_t)a * 512)     = t0;
        *reinterpret_cast<float4*>(base + (size_t)a * 512 + 4) = t1;
    }
}

// ---------------------------------------------------------------------------
// One CTA = one batch n, one 16x16 tile of low-res positions.
// 128 threads, each handling 2 positions (adjacent rows pA, pA+1).
// ---------------------------------------------------------------------------
__global__ void __launch_bounds__(NTHREADS, 3)
sr_kernel(const float* __restrict__ gx0, const float* __restrict__ gx1,
          const float* __restrict__ gx2, const float* __restrict__ gw,
          float* __restrict__ out)
{
    extern __shared__ float sm[];
    float* s_w  = sm;              // 189*64 = 12096 floats
    float* s_x0 = s_w + 12096;     // 18*18  = 324
    float* s_x1 = s_x0 + 324;      // 36*36  = 1296
    float* s_x2 = s_x1 + 1296;     // 72*72  = 5184   (total 18900 floats = 75600 B)

    const int tid = threadIdx.x;
    const int n  = blockIdx.z;
    const int i0 = blockIdx.y * 16;
    const int j0 = blockIdx.x * 16;

    // --- stage weights (broadcast-reused by all taps) ---
    {
        const float4* wg = reinterpret_cast<const float4*>(gw);
        float4* ws = reinterpret_cast<float4*>(s_w);
        for (int idx = tid; idx < 3024; idx += NTHREADS) ws[idx] = wg[idx];
    }
    // --- stage x0 patch: rows i0-1..i0+16, cols j0-1..j0+16 ---
    {
        const float* src = gx0 + n * 4096;
        for (int idx = tid; idx < 18 * 18; idx += NTHREADS) {
            int r = idx / 18, c = idx - r * 18;
            int gi = i0 - 1 + r, gj = j0 - 1 + c;
            float v = 0.0f;
            if ((unsigned)gi < 64u && (unsigned)gj < 64u) v = src[gi * 64 + gj];
            s_x0[idx] = v;
        }
    }
    // --- stage x1 patch: rows 2*i0-2 .. +35, cols 2*j0-2 .. +35 ---
    {
        const float* src = gx1 + n * 16384;
        for (int idx = tid; idx < 36 * 36; idx += NTHREADS) {
            int r = idx / 36, c = idx - r * 36;
            int gi = 2 * i0 - 2 + r, gj = 2 * j0 - 2 + c;
            float v = 0.0f;
            if ((unsigned)gi < 128u && (unsigned)gj < 128u) v = src[gi * 128 + gj];
            s_x1[idx] = v;
        }
    }
    // --- stage x2 patch: rows 4*i0-4 .. +71, cols 4*j0-4 .. +71 ---
    {
        const float* src = gx2 + n * 65536;
        for (int idx = tid; idx < 72 * 72; idx += NTHREADS) {
            int r = idx / 72, c = idx - r * 72;
            int gi = 4 * i0 - 4 + r, gj = 4 * j0 - 4 + c;
            float v = 0.0f;
            if ((unsigned)gi < 256u && (unsigned)gj < 256u) v = src[gi * 256 + gj];
            s_x2[idx] = v;
        }
    }
    __syncthreads();

    const int tj = tid & 15;           // tile column 0..15
    const int pA = (tid >> 4) * 2;     // tile row of position A (0,2,...,14)
    const int pB = pA + 1;

    unsigned long long accA[32], accB[32];
#pragma unroll
    for (int q = 0; q < 32; ++q) { accA[q] = 0ull; accB[q] = 0ull; }

    const float* wk = s_w;

    // layer 0: 3x3 taps, patch row index = p + di, col = tj + dj
#pragma unroll 1
    for (int di = 0; di < 3; ++di) {
        const float* rA = s_x0 + (pA + di) * 18 + tj;
        const float* rB = s_x0 + (pB + di) * 18 + tj;
#pragma unroll 1
        for (int dj = 0; dj < 3; ++dj) {
            fma_tap(accA, accB, wk, rA[dj], rB[dj]);
            wk += 64;
        }
    }
    // layer 1: 6x6 taps, patch row index = 2p + di, col = 2*tj + dj
#pragma unroll 1
    for (int di = 0; di < 6; ++di) {
        const float* rA = s_x1 + (2 * pA + di) * 36 + 2 * tj;
        const float* rB = s_x1 + (2 * pB + di) * 36 + 2 * tj;
#pragma unroll 1
        for (int dj = 0; dj < 6; ++dj) {
            fma_tap(accA, accB, wk, rA[dj], rB[dj]);
            wk += 64;
        }
    }
    // layer 2: 12x12 taps, patch row index = 4p + di, col = 4*tj + dj
#pragma unroll 1
    for (int di = 0; di < 12; ++di) {
        const float* rA = s_x2 + (4 * pA + di) * 72 + 4 * tj;
        const float* rB = s_x2 + (4 * pB + di) * 72 + 4 * tj;
#pragma unroll 1
        for (int dj = 0; dj < 12; ++dj) {
            fma_tap(accA, accB, wk, rA[dj], rB[dj]);
            wk += 64;
        }
    }

    const float xselA = s_x0[(pA + 1) * 18 + tj + 1];
    const float xselB = s_x0[(pB + 1) * 18 + tj + 1];

    finish_pos(out, n, i0 + pA, j0 + tj, accA, xselA);
    finish_pos(out, n, i0 + pB, j0 + tj, accB, xselB);
}

extern "C" void kernel_launch(void* const* d_in, const int* in_sizes, int n_in,
                              void* d_out, int out_size)
{
    const float* x0 = (const float*)d_in[0];
    const float* x1 = (const float*)d_in[1];
    const float* x2 = (const float*)d_in[2];
const float* w  = (const float*)d_in[3];
    float* out = (float*)d_out;

    const int smem_bytes = 18900 * (int)sizeof(float);  // 75600 B > 48KB -> opt-in
    cudaFuncSetAttribute(sr_kernel, cudaFuncAttributeMaxDynamicSharedMemorySize,
                         smem_bytes);

    dim3 grid(4, 4, 64);   // (j-tiles, i-tiles, batch)
    sr_kernel<<<grid, NTHREADS, smem_bytes>>>(x0, x1, x2, w, out);
}